// round 6
// baseline (speedup 1.0000x reference)
#include <cuda_runtime.h>
#include <cuda_fp16.h>
#include <math.h>

#define SS 512   // seq len
#define BB 64    // batch
#define HH 512   // hidden
#define II 512   // input
#define NC 64    // CTAs per direction in recurrent kernel

// ---------------- device scratch (no allocs allowed) ----------------
__device__ __half g_x16[BB * SS][II];        // fp16 copy of x, 33.5 MB
__device__ __half g_w16[8][HH][II];          // W transposed [z][n][k], 4.2 MB
__device__ __half g_xw16[8][BB * SS][HH];    // xw fp16, 268 MB
__device__ __half g_h16[2][2][BB][HH];       // h double buffer per direction
__device__ unsigned int g_ck[2][4];          // per-chunk production counters

// ---------------- PTX helpers ----------------
__device__ __forceinline__ void mma16816(float* c, const unsigned* a, const unsigned* b) {
    asm volatile(
        "mma.sync.aligned.m16n8k16.row.col.f32.f16.f16.f32 "
        "{%0,%1,%2,%3}, {%4,%5,%6,%7}, {%8,%9}, {%0,%1,%2,%3};\n"
        : "+f"(c[0]), "+f"(c[1]), "+f"(c[2]), "+f"(c[3])
        : "r"(a[0]), "r"(a[1]), "r"(a[2]), "r"(a[3]), "r"(b[0]), "r"(b[1]));
}

__device__ __forceinline__ void ldmx4(unsigned* a, const void* p) {
    unsigned addr = (unsigned)__cvta_generic_to_shared(p);
    asm volatile("ldmatrix.sync.aligned.m8n8.x4.shared.b16 {%0,%1,%2,%3}, [%4];"
                 : "=r"(a[0]), "=r"(a[1]), "=r"(a[2]), "=r"(a[3]) : "r"(addr));
}

__device__ __forceinline__ void cpa16(void* s, const void* g) {
    unsigned sa = (unsigned)__cvta_generic_to_shared(s);
    asm volatile("cp.async.cg.shared.global [%0], [%1], 16;" :: "r"(sa), "l"(g));
}
#define CP_COMMIT() asm volatile("cp.async.commit_group;")
#define CP_WAIT(n)  asm volatile("cp.async.wait_group %0;" :: "n"(n))

__device__ __forceinline__ float sig_fast(float x) {
    return __fdividef(1.0f, 1.0f + __expf(-x));
}
__device__ __forceinline__ float tanh_fast(float x) {
    // 1 - 2/(e^{2x}+1); stable at both extremes (inf -> 1, 0 -> -1)
    return 1.0f - __fdividef(2.0f, __expf(2.0f * x) + 1.0f);
}

// ---------------- init: reset counters every launch ----------------
__global__ void init_kernel() {
    g_ck[0][0] = 0; g_ck[0][1] = 0; g_ck[0][2] = 0; g_ck[0][3] = 0;
    g_ck[1][0] = 0; g_ck[1][1] = 0; g_ck[1][2] = 0; g_ck[1][3] = 0;
}

// ---------------- converts: x -> fp16, W -> fp16 transposed ----------------
__global__ __launch_bounds__(256) void cvt_x_kernel(const float* __restrict__ x) {
    int i4 = blockIdx.x * 256 + threadIdx.x;   // 4 floats per thread
    float4 v = *(const float4*)&x[(size_t)i4 * 4];
    __half2* dst = (__half2*)&g_x16[0][0];
    dst[i4 * 2]     = __floats2half2_rn(v.x, v.y);
    dst[i4 * 2 + 1] = __floats2half2_rn(v.z, v.w);
}

__global__ __launch_bounds__(256) void cvt_w_kernel(
    const float* __restrict__ Wf, const float* __restrict__ Wb) {
    const int z = blockIdx.z;
    const float* W = (z < 4 ? Wf : Wb) + (size_t)(z & 3) * II * HH;
    __shared__ float t[32][33];
    const int tx = threadIdx.x & 31, ty = threadIdx.x >> 5;  // 32 x 8
    const int k0 = blockIdx.y * 32, n0 = blockIdx.x * 32;
    #pragma unroll
    for (int i = 0; i < 4; i++)
        t[ty + 8 * i][tx] = W[(size_t)(k0 + ty + 8 * i) * HH + n0 + tx];
    __syncthreads();
    #pragma unroll
    for (int i = 0; i < 4; i++)
        g_w16[z][n0 + ty + 8 * i][k0 + tx] = __float2half_rn(t[tx][ty + 8 * i]);
}

// ---------------- phase 1: input projection GEMM (fp16, cp.async 2-stage) ----------------
// xw16[z][m][h] = sum_k x16[m][k] * w16[z][h][k] + bias[h]
// CTA 128(M) x 64(N), K-chunk 64, 256 thr = 8 warps (4m x 2n), warp tile 32x32.
__global__ __launch_bounds__(256) void proj_kernel(
    const float* __restrict__ bf, const float* __restrict__ bb)
{
    const int z = blockIdx.z;
    const float* bias = (z < 4 ? bf : bb) + (z & 3) * HH;
    const int m0 = blockIdx.x * 128;
    const int n0 = blockIdx.y * 64;

    extern __shared__ __align__(16) __half psm[];
    __half* As = psm;                 // [2][128][72]
    __half* Bs = psm + 2 * 128 * 72;  // [2][64][72]

    const int tid  = threadIdx.x;
    const int lane = tid & 31;
    const int wid  = tid >> 5;
    const int wm   = wid & 3;
    const int wn   = wid >> 2;
    const int arow = (lane & 7) | (((lane >> 3) & 1) << 3);
    const int acol = (lane >> 4) << 3;

    float acc[2][4][4];
    #pragma unroll
    for (int i = 0; i < 2; i++)
        #pragma unroll
        for (int jj = 0; jj < 4; jj++)
            #pragma unroll
            for (int q = 0; q < 4; q++) acc[i][jj][q] = 0.f;

    auto issue = [&](int st, int kc) {
        __half* a = As + st * 128 * 72;
        __half* b = Bs + st * 64 * 72;
        #pragma unroll
        for (int w = 0; w < 4; w++) {           // A: 128 rows x 8 units
            int f = tid + w * 256;
            int row = f >> 3, u = f & 7;
            cpa16(&a[row * 72 + u * 8], &g_x16[m0 + row][kc + u * 8]);
        }
        #pragma unroll
        for (int w = 0; w < 2; w++) {           // B: 64 rows x 8 units
            int f = tid + w * 256;
            int row = f >> 3, u = f & 7;
            cpa16(&b[row * 72 + u * 8], &g_w16[z][n0 + row][kc + u * 8]);
        }
        CP_COMMIT();
    };

    issue(0, 0);
    for (int kb = 0; kb < 8; kb++) {
        const int cur = kb & 1;
        if (kb < 7) { issue(cur ^ 1, (kb + 1) * 64); CP_WAIT(1); }
        else        { CP_WAIT(0); }
        __syncthreads();
        const __half* a0 = As + cur * 128 * 72;
        const __half* b0 = Bs + cur * 64 * 72;
        #pragma unroll
        for (int k16 = 0; k16 < 4; k16++) {
            unsigned a[2][4], b[4][2];
            #pragma unroll
            for (int mt = 0; mt < 2; mt++)
                ldmx4(a[mt], &a0[(wm * 32 + mt * 16 + arow) * 72 + k16 * 16 + acol]);
            #pragma unroll
            for (int nt = 0; nt < 4; nt++) {
                const __half* bp = &b0[(wn * 32 + nt * 8 + (lane >> 2)) * 72 + k16 * 16 + ((lane & 3) << 1)];
                b[nt][0] = *(const unsigned*)bp;
                b[nt][1] = *(const unsigned*)(bp + 8);
            }
            #pragma unroll
            for (int mt = 0; mt < 2; mt++)
                #pragma unroll
                for (int nt = 0; nt < 4; nt++)
                    mma16816(acc[mt][nt], a[mt], b[nt]);
        }
        __syncthreads();
    }

    // epilogue: add bias, store fp16 (half2)
    #pragma unroll
    for (int mt = 0; mt < 2; mt++) {
        #pragma unroll
        for (int nt = 0; nt < 4; nt++) {
            int n = n0 + wn * 32 + nt * 8 + ((lane & 3) << 1);
            float bx = bias[n], by = bias[n + 1];
            int mA = m0 + wm * 32 + mt * 16 + (lane >> 2);
            *(__half2*)&g_xw16[z][mA][n]     = __floats2half2_rn(acc[mt][nt][0] + bx, acc[mt][nt][1] + by);
            *(__half2*)&g_xw16[z][mA + 8][n] = __floats2half2_rn(acc[mt][nt][2] + bx, acc[mt][nt][3] + by);
        }
    }
}

// ---------------- fine-grained chunk wait ----------------
__device__ __forceinline__ void wait_chunk(int dir, int c, unsigned tgt) {
    if (threadIdx.x == 0) {
        const volatile unsigned* p = &g_ck[dir][c];
        while (*p < tgt) { __nanosleep(32); }
        __threadfence();
    }
    __syncthreads();
}

// ---------------- phase 2: persistent recurrent kernel ----------------
// 128 CTAs: dir = bid/64, slice = bid%64 -> 8 h-cols. Chunk c (128 cols) is
// produced by CTAs 16c..16c+15; consumers gate each cp.async chunk on g_ck.
__device__ __forceinline__ void issue_chunk(__half* As, const __half* hprev, int ch, int tid) {
    const int kc = ch * 128;
    #pragma unroll
    for (int w = 0; w < 8; w++) {
        int flat = tid + w * 128;
        int row = flat >> 4;
        int c16 = flat & 15;
        cpa16(&As[row * 520 + kc + c16 * 8], &hprev[row * 512 + kc + c16 * 8]);
    }
    CP_COMMIT();
}

__global__ void __launch_bounds__(128, 1) lstm_kernel(
    const float* __restrict__ Uf, const float* __restrict__ Ub,
    float* __restrict__ out)
{
    const int dir = blockIdx.x >> 6;
    const int slice = blockIdx.x & 63;
    const int h0 = slice * 8;
    const int mychunk = slice >> 4;

    extern __shared__ __align__(16) char smraw[];
    __half* As  = (__half*)smraw;            // [64][520]
    __half* Us  = As + 64 * 520;             // [32][520]
    float*  pre = (float*)(Us + 32 * 520);   // [4][64][10]

    const int tid  = threadIdx.x;
    const int lane = tid & 31;
    const int wid  = tid >> 5;
    const int wm   = wid & 1;
    const int wn   = wid >> 1;
    const int j    = tid & 7;
    const int b0j  = (tid >> 3) * 4;
    const int arow = (lane & 7) | (((lane >> 3) & 1) << 3);
    const int acol = (lane >> 4) << 3;

    const float* U = dir ? Ub : Uf;   // [4][HH][HH]

    // U slice -> fp16 smem
    for (int idx = tid; idx < 32 * 512; idx += 128) {
        int c = idx & 31, k = idx >> 5;
        Us[c * 520 + k] = __float2half_rn(U[((size_t)(c >> 3) * HH + k) * HH + h0 + (c & 7)]);
    }
    // zero h buffer 0 for this slice, then signal production of h_0
    for (int idx = tid; idx < 512; idx += 128) {
        int b = idx >> 3, jj = idx & 7;
        g_h16[dir][0][b][h0 + jj] = __float2half_rn(0.f);
    }
    __threadfence();
    __syncthreads();
    if (tid == 0) atomicAdd(&g_ck[dir][mychunk], 1u);

    float creg[4] = {0.f, 0.f, 0.f, 0.f};

    for (int t = 0; t < SS; t++) {
        const int s = dir ? (SS - 1 - t) : t;
        const __half* hprev = &g_h16[dir][t & 1][0][0];
        const unsigned tgt = 16u * (unsigned)(t + 1);

        wait_chunk(dir, 0, tgt); issue_chunk(As, hprev, 0, tid);
        wait_chunk(dir, 1, tgt); issue_chunk(As, hprev, 1, tid);

        // xw prefetch (fp16)
        float xr[4][4];
        #pragma unroll
        for (int g2 = 0; g2 < 4; g2++)
            #pragma unroll
            for (int i = 0; i < 4; i++)
                xr[i][g2] = __half2float(g_xw16[dir * 4 + g2][(size_t)(b0j + i) * 512 + s][h0 + j]);

        float acc[2][2][4];
        #pragma unroll
        for (int a1 = 0; a1 < 2; a1++)
            #pragma unroll
            for (int a2 = 0; a2 < 2; a2++)
                #pragma unroll
                for (int q = 0; q < 4; q++) acc[a1][a2][q] = 0.f;

        #pragma unroll
        for (int ch = 0; ch < 4; ch++) {
            if (ch < 3) CP_WAIT(1); else CP_WAIT(0);
            __syncthreads();
            const int kc = ch * 128;
            #pragma unroll
            for (int k16 = 0; k16 < 8; k16++) {
                const int k0 = kc + k16 * 16;
                unsigned a[2][4], b[2][2];
                #pragma unroll
                for (int mt = 0; mt < 2; mt++)
                    ldmx4(a[mt], &As[(wm * 32 + mt * 16 + arow) * 520 + k0 + acol]);
                #pragma unroll
                for (int nt = 0; nt < 2; nt++) {
                    const __half* bp = &Us[(wn * 16 + nt * 8 + (lane >> 2)) * 520 + k0 + ((lane & 3) << 1)];
                    b[nt][0] = *(const unsigned*)bp;
                    b[nt][1] = *(const unsigned*)(bp + 8);
                }
                #pragma unroll
                for (int mt = 0; mt < 2; mt++)
                    #pragma unroll
                    for (int nt = 0; nt < 2; nt++)
                        mma16816(acc[mt][nt], a[mt], b[nt]);
            }
            // interleave waits/issues for remaining chunks with compute
            if (ch == 0) { wait_chunk(dir, 2, tgt); issue_chunk(As, hprev, 2, tid); }
            if (ch == 1) { wait_chunk(dir, 3, tgt); issue_chunk(As, hprev, 3, tid); }
        }

        // gate exchange: frags -> pre[gate][b][j]
        #pragma unroll
        for (int mt = 0; mt < 2; mt++) {
            #pragma unroll
            for (int nt = 0; nt < 2; nt++) {
                int gate = wn * 2 + nt;
                int jloc = (lane & 3) << 1;
                int b = wm * 32 + mt * 16 + (lane >> 2);
                *(float2*)&pre[(gate * 64 + b) * 10 + jloc]     = make_float2(acc[mt][nt][0], acc[mt][nt][1]);
                *(float2*)&pre[(gate * 64 + b + 8) * 10 + jloc] = make_float2(acc[mt][nt][2], acc[mt][nt][3]);
            }
        }
        __syncthreads();

        // pointwise LSTM cell (gate order f,g,i,o); c lives in registers
        __half* hnext = &g_h16[dir][(t + 1) & 1][0][0];
        const int hc = h0 + j;
        #pragma unroll
        for (int i = 0; i < 4; i++) {
            const int b = b0j + i;
            float pf = pre[(0 * 64 + b) * 10 + j] + xr[i][0];
            float pg = pre[(1 * 64 + b) * 10 + j] + xr[i][1];
            float pi = pre[(2 * 64 + b) * 10 + j] + xr[i][2];
            float po = pre[(3 * 64 + b) * 10 + j] + xr[i][3];
            float fg = sig_fast(pf);
            float gg = tanh_fast(pg);
            float ig = sig_fast(pi);
            float og = sig_fast(po);
            creg[i] = creg[i] * fg + gg * ig;
            float hn = og * tanh_fast(creg[i]);
            hnext[b * HH + hc] = __float2half_rn(hn);
            out[(size_t)((s << 6) + b) * 1024 + dir * HH + hc] = hn;
        }

        __threadfence();
        __syncthreads();
        if (tid == 0) atomicAdd(&g_ck[dir][mychunk], 1u);
    }
}

// ---------------- phase 3: finalize h_f / h_b from mask ----------------
__global__ void final_kernel(const unsigned char* __restrict__ mask,
                             float* __restrict__ out)
{
    const int b = blockIdx.x;
    const int tid = threadIdx.x;

    __shared__ int mode;  // 1 if mask stored as int32, 0 if uint8
    if (tid == 0)
        mode = (mask[0] == 1 && mask[1] == 0 && mask[2] == 0 && mask[3] == 0) ? 1 : 0;
    __syncthreads();

    int v;
    if (mode) {
        const int* mi = (const int*)mask;
        v = (mi[b * SS + tid] != 0) ? 1 : 0;
    } else {
        v = (mask[b * SS + tid] != 0) ? 1 : 0;
    }
    int len = __syncthreads_count(v);
    int idx = (len > 0) ? (len - 1) : 0;

    float* hf = out + (size_t)SS * BB * 1024;
    float* hb = hf + (size_t)BB * HH;
    hf[b * HH + tid] = out[(size_t)((idx << 6) + b) * 1024 + tid];
    hb[b * HH + tid] = out[(size_t)b * 1024 + HH + tid];
}

// ---------------- launch ----------------
extern "C" void kernel_launch(void* const* d_in, const int* in_sizes, int n_in,
                              void* d_out, int out_size)
{
    const float* x  = (const float*)d_in[0];
    const unsigned char* mask = (const unsigned char*)d_in[1];
    const float* Uf = (const float*)d_in[2];
    const float* Wf = (const float*)d_in[3];
    const float* bf = (const float*)d_in[4];
    const float* Ub = (const float*)d_in[5];
    const float* Wb = (const float*)d_in[6];
    const float* bb = (const float*)d_in[7];
    float* out = (float*)d_out;

    init_kernel<<<1, 32>>>();

    cvt_x_kernel<<<BB * SS * II / 4 / 256, 256>>>(x);
    dim3 wg(16, 16, 8);
    cvt_w_kernel<<<wg, 256>>>(Wf, Wb);

    size_t psmem = (size_t)(2 * 128 * 72 + 2 * 64 * 72) * sizeof(__half);  // 55,296 B
    cudaFuncSetAttribute(proj_kernel, cudaFuncAttributeMaxDynamicSharedMemorySize, (int)psmem);
    dim3 pg(BB * SS / 128, HH / 64, 8);   // (256, 8, 8)
    proj_kernel<<<pg, 256, psmem>>>(bf, bb);

    size_t smem = (size_t)(64 * 520 + 32 * 520) * sizeof(__half)
                + (size_t)(4 * 64 * 10) * sizeof(float);   // 110,080 B
    cudaFuncSetAttribute(lstm_kernel, cudaFuncAttributeMaxDynamicSharedMemorySize, (int)smem);
    lstm_kernel<<<128, 128, smem>>>(Uf, Ub, out);

    final_kernel<<<BB, SS>>>(mask, out);
}

// round 7
// speedup vs baseline: 1.3716x; 1.3716x over previous
#include <cuda_runtime.h>
#include <cuda_fp16.h>
#include <math.h>

#define SS 512   // seq len
#define BB 64    // batch
#define HH 512   // hidden
#define II 512   // input
#define NC 64    // CTAs per direction in recurrent kernel

// ---------------- device scratch (no allocs allowed) ----------------
__device__ __half g_x16[BB * SS][II];        // fp16 copy of x, 33.5 MB
__device__ __half g_w16[8][HH][II];          // W transposed [z][n][k], 4.2 MB
__device__ __half g_xw16[8][BB * SS][HH];    // xw fp16, 268 MB
__device__ __half g_h16[2][2][BB][HH];       // h double buffer per direction
__device__ unsigned int g_cnt[2];
__device__ unsigned int g_rel[2];

// ---------------- PTX helpers ----------------
__device__ __forceinline__ void mma16816(float* c, const unsigned* a, const unsigned* b) {
    asm volatile(
        "mma.sync.aligned.m16n8k16.row.col.f32.f16.f16.f32 "
        "{%0,%1,%2,%3}, {%4,%5,%6,%7}, {%8,%9}, {%0,%1,%2,%3};\n"
        : "+f"(c[0]), "+f"(c[1]), "+f"(c[2]), "+f"(c[3])
        : "r"(a[0]), "r"(a[1]), "r"(a[2]), "r"(a[3]), "r"(b[0]), "r"(b[1]));
}

__device__ __forceinline__ void ldmx4(unsigned* a, const void* p) {
    unsigned addr = (unsigned)__cvta_generic_to_shared(p);
    asm volatile("ldmatrix.sync.aligned.m8n8.x4.shared.b16 {%0,%1,%2,%3}, [%4];"
                 : "=r"(a[0]), "=r"(a[1]), "=r"(a[2]), "=r"(a[3]) : "r"(addr));
}

__device__ __forceinline__ void cpa16(void* s, const void* g) {
    unsigned sa = (unsigned)__cvta_generic_to_shared(s);
    asm volatile("cp.async.cg.shared.global [%0], [%1], 16;" :: "r"(sa), "l"(g));
}
#define CP_COMMIT() asm volatile("cp.async.commit_group;")
#define CP_WAIT(n)  asm volatile("cp.async.wait_group %0;" :: "n"(n))

__device__ __forceinline__ float sig_fast(float x) {
    return __fdividef(1.0f, 1.0f + __expf(-x));
}
__device__ __forceinline__ float tanh_fast(float x) {
    return 1.0f - __fdividef(2.0f, __expf(2.0f * x) + 1.0f);
}

// ---------------- barrier: release/acquire, split arrive/wait ----------------
__device__ __forceinline__ void bar_arrive(int dir, unsigned gen) {
    // caller must __syncthreads() before (h stores visible at CTA scope)
    if (threadIdx.x == 0) {
        unsigned old;
        asm volatile("atom.acq_rel.gpu.global.add.u32 %0, [%1], 1;"
                     : "=r"(old) : "l"(&g_cnt[dir]) : "memory");
        if (old == NC - 1) {
            g_cnt[dir] = 0;   // safe: published by the release store below
            asm volatile("st.release.gpu.global.u32 [%0], %1;"
                         :: "l"(&g_rel[dir]), "r"(gen) : "memory");
        }
    }
}
__device__ __forceinline__ void bar_wait(int dir, unsigned gen) {
    if (threadIdx.x == 0) {
        unsigned v;
        do {
            asm volatile("ld.acquire.gpu.global.u32 %0, [%1];"
                         : "=r"(v) : "l"(&g_rel[dir]) : "memory");
        } while (v < gen);
    }
    __syncthreads();
}

// ---------------- init: reset barrier state every launch ----------------
__global__ void init_kernel() {
    g_cnt[0] = 0; g_cnt[1] = 0;
    g_rel[0] = 0; g_rel[1] = 0;
}

// ---------------- converts: x -> fp16, W -> fp16 transposed ----------------
__global__ __launch_bounds__(256) void cvt_x_kernel(const float* __restrict__ x) {
    int i4 = blockIdx.x * 256 + threadIdx.x;
    float4 v = *(const float4*)&x[(size_t)i4 * 4];
    __half2* dst = (__half2*)&g_x16[0][0];
    dst[i4 * 2]     = __floats2half2_rn(v.x, v.y);
    dst[i4 * 2 + 1] = __floats2half2_rn(v.z, v.w);
}

__global__ __launch_bounds__(256) void cvt_w_kernel(
    const float* __restrict__ Wf, const float* __restrict__ Wb) {
    const int z = blockIdx.z;
    const float* W = (z < 4 ? Wf : Wb) + (size_t)(z & 3) * II * HH;
    __shared__ float t[32][33];
    const int tx = threadIdx.x & 31, ty = threadIdx.x >> 5;  // 32 x 8
    const int k0 = blockIdx.y * 32, n0 = blockIdx.x * 32;
    #pragma unroll
    for (int i = 0; i < 4; i++)
        t[ty + 8 * i][tx] = W[(size_t)(k0 + ty + 8 * i) * HH + n0 + tx];
    __syncthreads();
    #pragma unroll
    for (int i = 0; i < 4; i++)
        g_w16[z][n0 + ty + 8 * i][k0 + tx] = __float2half_rn(t[tx][ty + 8 * i]);
}

// ---------------- phase 1: input projection GEMM (fp16, cp.async 2-stage) ----------------
__global__ __launch_bounds__(256) void proj_kernel(
    const float* __restrict__ bf, const float* __restrict__ bb)
{
    const int z = blockIdx.z;
    const float* bias = (z < 4 ? bf : bb) + (z & 3) * HH;
    const int m0 = blockIdx.x * 128;
    const int n0 = blockIdx.y * 64;

    extern __shared__ __align__(16) __half psm[];
    __half* As = psm;                 // [2][128][72]
    __half* Bs = psm + 2 * 128 * 72;  // [2][64][72]

    const int tid  = threadIdx.x;
    const int lane = tid & 31;
    const int wid  = tid >> 5;
    const int wm   = wid & 3;
    const int wn   = wid >> 2;
    const int arow = (lane & 7) | (((lane >> 3) & 1) << 3);
    const int acol = (lane >> 4) << 3;

    float acc[2][4][4];
    #pragma unroll
    for (int i = 0; i < 2; i++)
        #pragma unroll
        for (int jj = 0; jj < 4; jj++)
            #pragma unroll
            for (int q = 0; q < 4; q++) acc[i][jj][q] = 0.f;

    auto issue = [&](int st, int kc) {
        __half* a = As + st * 128 * 72;
        __half* b = Bs + st * 64 * 72;
        #pragma unroll
        for (int w = 0; w < 4; w++) {
            int f = tid + w * 256;
            int row = f >> 3, u = f & 7;
            cpa16(&a[row * 72 + u * 8], &g_x16[m0 + row][kc + u * 8]);
        }
        #pragma unroll
        for (int w = 0; w < 2; w++) {
            int f = tid + w * 256;
            int row = f >> 3, u = f & 7;
            cpa16(&b[row * 72 + u * 8], &g_w16[z][n0 + row][kc + u * 8]);
        }
        CP_COMMIT();
    };

    issue(0, 0);
    for (int kb = 0; kb < 8; kb++) {
        const int cur = kb & 1;
        if (kb < 7) { issue(cur ^ 1, (kb + 1) * 64); CP_WAIT(1); }
        else        { CP_WAIT(0); }
        __syncthreads();
        const __half* a0 = As + cur * 128 * 72;
        const __half* b0 = Bs + cur * 64 * 72;
        #pragma unroll
        for (int k16 = 0; k16 < 4; k16++) {
            unsigned a[2][4], b[4][2];
            #pragma unroll
            for (int mt = 0; mt < 2; mt++)
                ldmx4(a[mt], &a0[(wm * 32 + mt * 16 + arow) * 72 + k16 * 16 + acol]);
            #pragma unroll
            for (int nt = 0; nt < 4; nt++) {
                const __half* bp = &b0[(wn * 32 + nt * 8 + (lane >> 2)) * 72 + k16 * 16 + ((lane & 3) << 1)];
                b[nt][0] = *(const unsigned*)bp;
                b[nt][1] = *(const unsigned*)(bp + 8);
            }
            #pragma unroll
            for (int mt = 0; mt < 2; mt++)
                #pragma unroll
                for (int nt = 0; nt < 4; nt++)
                    mma16816(acc[mt][nt], a[mt], b[nt]);
        }
        __syncthreads();
    }

    #pragma unroll
    for (int mt = 0; mt < 2; mt++) {
        #pragma unroll
        for (int nt = 0; nt < 4; nt++) {
            int n = n0 + wn * 32 + nt * 8 + ((lane & 3) << 1);
            float bx = bias[n], by = bias[n + 1];
            int mA = m0 + wm * 32 + mt * 16 + (lane >> 2);
            *(__half2*)&g_xw16[z][mA][n]     = __floats2half2_rn(acc[mt][nt][0] + bx, acc[mt][nt][1] + by);
            *(__half2*)&g_xw16[z][mA + 8][n] = __floats2half2_rn(acc[mt][nt][2] + bx, acc[mt][nt][3] + by);
        }
    }
}

// ---------------- phase 2: persistent recurrent kernel ----------------
// 128 CTAs: dir = bid/64, slice = bid%64 -> 8 h-cols. 256 threads = 8 warps.
// GEMM: preact[64b x 32(4g x 8h)] = h16[64x512] @ Uslice[512x32]; warp tile 16x16.
__device__ __forceinline__ void issue_chunk(__half* As, const __half* hprev, int ch, int tid) {
    const int kc = ch * 128;
    #pragma unroll
    for (int w = 0; w < 4; w++) {
        int flat = tid + w * 256;          // 1024 x 16B = 64 rows x 256 B
        int row = flat >> 4;
        int c16 = flat & 15;
        cpa16(&As[row * 520 + kc + c16 * 8], &hprev[row * 512 + kc + c16 * 8]);
    }
    CP_COMMIT();
}

__global__ void __launch_bounds__(256, 1) lstm_kernel(
    const float* __restrict__ Uf, const float* __restrict__ Ub,
    float* __restrict__ out)
{
    const int dir = blockIdx.x >> 6;
    const int slice = blockIdx.x & 63;
    const int h0 = slice * 8;

    extern __shared__ __align__(16) char smraw[];
    __half* As  = (__half*)smraw;            // [64][520]
    __half* Us  = As + 64 * 520;             // [32][520]  col = g*8+j
    float*  pre = (float*)(Us + 32 * 520);   // [4][64][10]

    const int tid  = threadIdx.x;
    const int lane = tid & 31;
    const int wid  = tid >> 5;
    const int wm   = wid & 3;     // 16-row m tile (batches)
    const int wn   = wid >> 2;    // 16-col n tile (2 gates)
    const int arow = (lane & 7) | (((lane >> 3) & 1) << 3);
    const int acol = (lane >> 4) << 3;

    // pointwise mapping: 2 values/thread
    const int pb = tid >> 2;           // batch 0..63
    const int pj = (tid & 3) << 1;     // col pair 0,2,4,6

    const float* U = dir ? Ub : Uf;   // [4][HH][HH]

    // U slice -> fp16 smem
    for (int idx = tid; idx < 32 * 512; idx += 256) {
        int c = idx & 31, k = idx >> 5;
        Us[c * 520 + k] = __float2half_rn(U[((size_t)(c >> 3) * HH + k) * HH + h0 + (c & 7)]);
    }
    // zero h buffer 0 for this slice
    for (int idx = tid; idx < 512; idx += 256) {
        int b = idx >> 3, jj = idx & 7;
        g_h16[dir][0][b][h0 + jj] = __float2half_rn(0.f);
    }

    float creg[2] = {0.f, 0.f};

    __syncthreads();
    bar_arrive(dir, 1u);
    bar_wait(dir, 1u);

    for (int t = 0; t < SS; t++) {
        const int s = dir ? (SS - 1 - t) : t;
        const __half* hprev = &g_h16[dir][t & 1][0][0];

        issue_chunk(As, hprev, 0, tid);
        issue_chunk(As, hprev, 1, tid);

        // xw prefetch (vectorized half2 per gate)
        float2 xr[4];
        #pragma unroll
        for (int g2 = 0; g2 < 4; g2++)
            xr[g2] = __half22float2(*(const __half2*)&g_xw16[dir * 4 + g2][(size_t)pb * 512 + s][h0 + pj]);

        float acc[2][4];
        #pragma unroll
        for (int a2 = 0; a2 < 2; a2++)
            #pragma unroll
            for (int q = 0; q < 4; q++) acc[a2][q] = 0.f;

        #pragma unroll
        for (int ch = 0; ch < 4; ch++) {
            if (ch < 2)      { issue_chunk(As, hprev, ch + 2, tid); CP_WAIT(2); }
            else if (ch == 2) CP_WAIT(1);
            else              CP_WAIT(0);
            __syncthreads();
            const int kc = ch * 128;
            #pragma unroll
            for (int k16 = 0; k16 < 8; k16++) {
                const int k0 = kc + k16 * 16;
                unsigned a[4], b[2][2];
                ldmx4(a, &As[(wm * 16 + arow) * 520 + k0 + acol]);
                #pragma unroll
                for (int nt = 0; nt < 2; nt++) {
                    const __half* bp = &Us[(wn * 16 + nt * 8 + (lane >> 2)) * 520 + k0 + ((lane & 3) << 1)];
                    b[nt][0] = *(const unsigned*)bp;
                    b[nt][1] = *(const unsigned*)(bp + 8);
                }
                #pragma unroll
                for (int nt = 0; nt < 2; nt++)
                    mma16816(acc[nt], a, b[nt]);
            }
        }

        // gate exchange: frags -> pre[gate][b][j]
        #pragma unroll
        for (int nt = 0; nt < 2; nt++) {
            int gate = wn * 2 + nt;
            int jloc = (lane & 3) << 1;
            int b = wm * 16 + (lane >> 2);
            *(float2*)&pre[(gate * 64 + b) * 10 + jloc]     = make_float2(acc[nt][0], acc[nt][1]);
            *(float2*)&pre[(gate * 64 + b + 8) * 10 + jloc] = make_float2(acc[nt][2], acc[nt][3]);
        }
        __syncthreads();

        // pointwise LSTM cell (gate order f,g,i,o); 2 cols per thread
        __half* hnext = &g_h16[dir][(t + 1) & 1][0][0];
        float2 pf = *(float2*)&pre[(0 * 64 + pb) * 10 + pj];
        float2 pg = *(float2*)&pre[(1 * 64 + pb) * 10 + pj];
        float2 pi = *(float2*)&pre[(2 * 64 + pb) * 10 + pj];
        float2 po = *(float2*)&pre[(3 * 64 + pb) * 10 + pj];
        float hn[2];
        #pragma unroll
        for (int q = 0; q < 2; q++) {
            float f = sig_fast((q ? pf.y : pf.x) + (q ? xr[0].y : xr[0].x));
            float g = tanh_fast((q ? pg.y : pg.x) + (q ? xr[1].y : xr[1].x));
            float i = sig_fast((q ? pi.y : pi.x) + (q ? xr[2].y : xr[2].x));
            float o = sig_fast((q ? po.y : po.x) + (q ? xr[3].y : xr[3].x));
            creg[q] = creg[q] * f + g * i;
            hn[q] = o * tanh_fast(creg[q]);
        }
        *(__half2*)&hnext[pb * HH + h0 + pj] = __floats2half2_rn(hn[0], hn[1]);

        __syncthreads();                 // h stores visible CTA-wide
        bar_arrive(dir, (unsigned)(t + 2));

        // out store overlapped with barrier wait
        *(float2*)&out[(size_t)((s << 6) + pb) * 1024 + dir * HH + h0 + pj] = make_float2(hn[0], hn[1]);

        bar_wait(dir, (unsigned)(t + 2));
    }
}

// ---------------- phase 3: finalize h_f / h_b from mask ----------------
__global__ void final_kernel(const unsigned char* __restrict__ mask,
                             float* __restrict__ out)
{
    const int b = blockIdx.x;
    const int tid = threadIdx.x;

    __shared__ int mode;  // 1 if mask stored as int32, 0 if uint8
    if (tid == 0)
        mode = (mask[0] == 1 && mask[1] == 0 && mask[2] == 0 && mask[3] == 0) ? 1 : 0;
    __syncthreads();

    int v;
    if (mode) {
        const int* mi = (const int*)mask;
        v = (mi[b * SS + tid] != 0) ? 1 : 0;
    } else {
        v = (mask[b * SS + tid] != 0) ? 1 : 0;
    }
    int len = __syncthreads_count(v);
    int idx = (len > 0) ? (len - 1) : 0;

    float* hf = out + (size_t)SS * BB * 1024;
    float* hb = hf + (size_t)BB * HH;
    hf[b * HH + tid] = out[(size_t)((idx << 6) + b) * 1024 + tid];
    hb[b * HH + tid] = out[(size_t)b * 1024 + HH + tid];
}

// ---------------- launch ----------------
extern "C" void kernel_launch(void* const* d_in, const int* in_sizes, int n_in,
                              void* d_out, int out_size)
{
    const float* x  = (const float*)d_in[0];
    const unsigned char* mask = (const unsigned char*)d_in[1];
    const float* Uf = (const float*)d_in[2];
    const float* Wf = (const float*)d_in[3];
    const float* bf = (const float*)d_in[4];
    const float* Ub = (const float*)d_in[5];
    const float* Wb = (const float*)d_in[6];
    const float* bb = (const float*)d_in[7];
    float* out = (float*)d_out;

    init_kernel<<<1, 32>>>();

    cvt_x_kernel<<<BB * SS * II / 4 / 256, 256>>>(x);
    dim3 wg(16, 16, 8);
    cvt_w_kernel<<<wg, 256>>>(Wf, Wb);

    size_t psmem = (size_t)(2 * 128 * 72 + 2 * 64 * 72) * sizeof(__half);  // 55,296 B
    cudaFuncSetAttribute(proj_kernel, cudaFuncAttributeMaxDynamicSharedMemorySize, (int)psmem);
    dim3 pg(BB * SS / 128, HH / 64, 8);   // (256, 8, 8)
    proj_kernel<<<pg, 256, psmem>>>(bf, bb);

    size_t smem = (size_t)(64 * 520 + 32 * 520) * sizeof(__half)
                + (size_t)(4 * 64 * 10) * sizeof(float);   // 110,080 B
    cudaFuncSetAttribute(lstm_kernel, cudaFuncAttributeMaxDynamicSharedMemorySize, (int)smem);
    lstm_kernel<<<128, 256, smem>>>(Uf, Ub, out);

    final_kernel<<<BB, SS>>>(mask, out);
}

// round 8
// speedup vs baseline: 1.5640x; 1.1402x over previous
#include <cuda_runtime.h>
#include <cuda_fp16.h>
#include <math.h>

#define SS 512   // seq len
#define BB 64    // batch
#define HH 512   // hidden
#define II 512   // input
#define NC 64    // CTAs per direction in recurrent kernel

// ---------------- device scratch (no allocs allowed) ----------------
__device__ __half g_x16[BB * SS][II];        // fp16 copy of x, 33.5 MB
__device__ __half g_w16[8][HH][II];          // W transposed [z][n][k], 4.2 MB
__device__ __half g_xw16[8][BB * SS][HH];    // xw fp16, 268 MB
__device__ __half g_h16[2][2][BB][HH];       // h double buffer per direction
__device__ unsigned int g_flag[2][NC][8];    // per-CTA progress flags, 32B padded

// ---------------- PTX helpers ----------------
__device__ __forceinline__ void mma16816(float* c, const unsigned* a, const unsigned* b) {
    asm volatile(
        "mma.sync.aligned.m16n8k16.row.col.f32.f16.f16.f32 "
        "{%0,%1,%2,%3}, {%4,%5,%6,%7}, {%8,%9}, {%0,%1,%2,%3};\n"
        : "+f"(c[0]), "+f"(c[1]), "+f"(c[2]), "+f"(c[3])
        : "r"(a[0]), "r"(a[1]), "r"(a[2]), "r"(a[3]), "r"(b[0]), "r"(b[1]));
}

__device__ __forceinline__ void ldmx4(unsigned* a, const void* p) {
    unsigned addr = (unsigned)__cvta_generic_to_shared(p);
    asm volatile("ldmatrix.sync.aligned.m8n8.x4.shared.b16 {%0,%1,%2,%3}, [%4];"
                 : "=r"(a[0]), "=r"(a[1]), "=r"(a[2]), "=r"(a[3]) : "r"(addr));
}

__device__ __forceinline__ void cpa16(void* s, const void* g) {
    unsigned sa = (unsigned)__cvta_generic_to_shared(s);
    asm volatile("cp.async.cg.shared.global [%0], [%1], 16;" :: "r"(sa), "l"(g));
}
#define CP_COMMIT() asm volatile("cp.async.commit_group;")
#define CP_WAIT(n)  asm volatile("cp.async.wait_group %0;" :: "n"(n))

__device__ __forceinline__ float sig_fast(float x) {
    return __fdividef(1.0f, 1.0f + __expf(-x));
}
__device__ __forceinline__ float tanh_fast(float x) {
    return 1.0f - __fdividef(2.0f, __expf(2.0f * x) + 1.0f);
}

// ---------------- flag barrier: per-CTA slot, no atomics ----------------
// arrive: tid0 release-stores gen into its own slot (after __syncthreads).
__device__ __forceinline__ void flag_publish(int dir, int slice, unsigned gen) {
    if (threadIdx.x == 0)
        asm volatile("st.release.gpu.global.u32 [%0], %1;"
                     :: "l"(&g_flag[dir][slice][0]), "r"(gen) : "memory");
}
// wait: lanes 0..63 each poll one distinct flag (coalesced, 16 sectors/round).
__device__ __forceinline__ void flag_wait_all(int dir, unsigned gen) {
    if (threadIdx.x < NC) {
        const unsigned* p = &g_flag[dir][threadIdx.x][0];
        unsigned v;
        do {
            asm volatile("ld.acquire.gpu.global.u32 %0, [%1];"
                         : "=r"(v) : "l"(p) : "memory");
        } while (v < gen);
    }
    __syncthreads();
}

// ---------------- init: reset flags every launch ----------------
__global__ void init_kernel() {
    unsigned* p = &g_flag[0][0][0];
    for (int i = threadIdx.x; i < 2 * NC * 8; i += blockDim.x) p[i] = 0;
}

// ---------------- converts: x -> fp16, W -> fp16 transposed ----------------
__global__ __launch_bounds__(256) void cvt_x_kernel(const float* __restrict__ x) {
    int i4 = blockIdx.x * 256 + threadIdx.x;
    float4 v = *(const float4*)&x[(size_t)i4 * 4];
    __half2* dst = (__half2*)&g_x16[0][0];
    dst[i4 * 2]     = __floats2half2_rn(v.x, v.y);
    dst[i4 * 2 + 1] = __floats2half2_rn(v.z, v.w);
}

__global__ __launch_bounds__(256) void cvt_w_kernel(
    const float* __restrict__ Wf, const float* __restrict__ Wb) {
    const int z = blockIdx.z;
    const float* W = (z < 4 ? Wf : Wb) + (size_t)(z & 3) * II * HH;
    __shared__ float t[32][33];
    const int tx = threadIdx.x & 31, ty = threadIdx.x >> 5;  // 32 x 8
    const int k0 = blockIdx.y * 32, n0 = blockIdx.x * 32;
    #pragma unroll
    for (int i = 0; i < 4; i++)
        t[ty + 8 * i][tx] = W[(size_t)(k0 + ty + 8 * i) * HH + n0 + tx];
    __syncthreads();
    #pragma unroll
    for (int i = 0; i < 4; i++)
        g_w16[z][n0 + ty + 8 * i][k0 + tx] = __float2half_rn(t[tx][ty + 8 * i]);
}

// ---------------- phase 1: input projection GEMM (fp16, cp.async 2-stage) ----------------
__global__ __launch_bounds__(256) void proj_kernel(
    const float* __restrict__ bf, const float* __restrict__ bb)
{
    const int z = blockIdx.z;
    const float* bias = (z < 4 ? bf : bb) + (z & 3) * HH;
    const int m0 = blockIdx.x * 128;
    const int n0 = blockIdx.y * 64;

    extern __shared__ __align__(16) __half psm[];
    __half* As = psm;                 // [2][128][72]
    __half* Bs = psm + 2 * 128 * 72;  // [2][64][72]

    const int tid  = threadIdx.x;
    const int lane = tid & 31;
    const int wid  = tid >> 5;
    const int wm   = wid & 3;
    const int wn   = wid >> 2;
    const int arow = (lane & 7) | (((lane >> 3) & 1) << 3);
    const int acol = (lane >> 4) << 3;

    float acc[2][4][4];
    #pragma unroll
    for (int i = 0; i < 2; i++)
        #pragma unroll
        for (int jj = 0; jj < 4; jj++)
            #pragma unroll
            for (int q = 0; q < 4; q++) acc[i][jj][q] = 0.f;

    auto issue = [&](int st, int kc) {
        __half* a = As + st * 128 * 72;
        __half* b = Bs + st * 64 * 72;
        #pragma unroll
        for (int w = 0; w < 4; w++) {
            int f = tid + w * 256;
            int row = f >> 3, u = f & 7;
            cpa16(&a[row * 72 + u * 8], &g_x16[m0 + row][kc + u * 8]);
        }
        #pragma unroll
        for (int w = 0; w < 2; w++) {
            int f = tid + w * 256;
            int row = f >> 3, u = f & 7;
            cpa16(&b[row * 72 + u * 8], &g_w16[z][n0 + row][kc + u * 8]);
        }
        CP_COMMIT();
    };

    issue(0, 0);
    for (int kb = 0; kb < 8; kb++) {
        const int cur = kb & 1;
        if (kb < 7) { issue(cur ^ 1, (kb + 1) * 64); CP_WAIT(1); }
        else        { CP_WAIT(0); }
        __syncthreads();
        const __half* a0 = As + cur * 128 * 72;
        const __half* b0 = Bs + cur * 64 * 72;
        #pragma unroll
        for (int k16 = 0; k16 < 4; k16++) {
            unsigned a[2][4], b[4][2];
            #pragma unroll
            for (int mt = 0; mt < 2; mt++)
                ldmx4(a[mt], &a0[(wm * 32 + mt * 16 + arow) * 72 + k16 * 16 + acol]);
            #pragma unroll
            for (int nt = 0; nt < 4; nt++) {
                const __half* bp = &b0[(wn * 32 + nt * 8 + (lane >> 2)) * 72 + k16 * 16 + ((lane & 3) << 1)];
                b[nt][0] = *(const unsigned*)bp;
                b[nt][1] = *(const unsigned*)(bp + 8);
            }
            #pragma unroll
            for (int mt = 0; mt < 2; mt++)
                #pragma unroll
                for (int nt = 0; nt < 4; nt++)
                    mma16816(acc[mt][nt], a[mt], b[nt]);
        }
        __syncthreads();
    }

    #pragma unroll
    for (int mt = 0; mt < 2; mt++) {
        #pragma unroll
        for (int nt = 0; nt < 4; nt++) {
            int n = n0 + wn * 32 + nt * 8 + ((lane & 3) << 1);
            float bx = bias[n], by = bias[n + 1];
            int mA = m0 + wm * 32 + mt * 16 + (lane >> 2);
            *(__half2*)&g_xw16[z][mA][n]     = __floats2half2_rn(acc[mt][nt][0] + bx, acc[mt][nt][1] + by);
            *(__half2*)&g_xw16[z][mA + 8][n] = __floats2half2_rn(acc[mt][nt][2] + bx, acc[mt][nt][3] + by);
        }
    }
}

// ---------------- phase 2: persistent recurrent kernel ----------------
// 128 CTAs: dir = bid/64, slice = bid%64 -> 8 h-cols. 256 threads = 8 warps.
// GEMM: preact[64b x 32(4g x 8h)] = h16[64x512] @ Uslice[512x32]; warp tile 16x16.
__device__ __forceinline__ void issue_chunk(__half* As, const __half* hprev, int ch, int tid) {
    const int kc = ch * 128;
    #pragma unroll
    for (int w = 0; w < 4; w++) {
        int flat = tid + w * 256;          // 1024 x 16B = 64 rows x 256 B
        int row = flat >> 4;
        int c16 = flat & 15;
        cpa16(&As[row * 520 + kc + c16 * 8], &hprev[row * 512 + kc + c16 * 8]);
    }
    CP_COMMIT();
}

__global__ void __launch_bounds__(256, 1) lstm_kernel(
    const float* __restrict__ Uf, const float* __restrict__ Ub,
    float* __restrict__ out)
{
    const int dir = blockIdx.x >> 6;
    const int slice = blockIdx.x & 63;
    const int h0 = slice * 8;

    extern __shared__ __align__(16) char smraw[];
    __half* As  = (__half*)smraw;            // [64][520]
    __half* Us  = As + 64 * 520;             // [32][520]  col = g*8+j
    float*  pre = (float*)(Us + 32 * 520);   // [4][64][10]

    const int tid  = threadIdx.x;
    const int lane = tid & 31;
    const int wid  = tid >> 5;
    const int wm   = wid & 3;     // 16-row m tile (batches)
    const int wn   = wid >> 2;    // 16-col n tile (2 gates)
    const int arow = (lane & 7) | (((lane >> 3) & 1) << 3);
    const int acol = (lane >> 4) << 3;

    // pointwise mapping: 2 values/thread
    const int pb = tid >> 2;           // batch 0..63
    const int pj = (tid & 3) << 1;     // col pair 0,2,4,6

    const float* U = dir ? Ub : Uf;   // [4][HH][HH]

    // U slice -> fp16 smem
    for (int idx = tid; idx < 32 * 512; idx += 256) {
        int c = idx & 31, k = idx >> 5;
        Us[c * 520 + k] = __float2half_rn(U[((size_t)(c >> 3) * HH + k) * HH + h0 + (c & 7)]);
    }
    // zero h buffer 0 for this slice
    for (int idx = tid; idx < 512; idx += 256) {
        int b = idx >> 3, jj = idx & 7;
        g_h16[dir][0][b][h0 + jj] = __float2half_rn(0.f);
    }

    float creg[2] = {0.f, 0.f};

    __syncthreads();
    flag_publish(dir, slice, 1u);

    // prefetch xw for t=0 (independent of barrier)
    float2 xr[4];
    {
        const int s0 = dir ? (SS - 1) : 0;
        #pragma unroll
        for (int g2 = 0; g2 < 4; g2++)
            xr[g2] = __half22float2(*(const __half2*)&g_xw16[dir * 4 + g2][(size_t)pb * 512 + s0][h0 + pj]);
    }

    flag_wait_all(dir, 1u);

    for (int t = 0; t < SS; t++) {
        const int s = dir ? (SS - 1 - t) : t;
        const __half* hprev = &g_h16[dir][t & 1][0][0];

        issue_chunk(As, hprev, 0, tid);
        issue_chunk(As, hprev, 1, tid);

        float acc[2][4];
        #pragma unroll
        for (int a2 = 0; a2 < 2; a2++)
            #pragma unroll
            for (int q = 0; q < 4; q++) acc[a2][q] = 0.f;

        #pragma unroll
        for (int ch = 0; ch < 4; ch++) {
            if (ch < 2)      { issue_chunk(As, hprev, ch + 2, tid); CP_WAIT(2); }
            else if (ch == 2) CP_WAIT(1);
            else              CP_WAIT(0);
            __syncthreads();
            const int kc = ch * 128;
            #pragma unroll
            for (int k16 = 0; k16 < 8; k16++) {
                const int k0 = kc + k16 * 16;
                unsigned a[4], b[2][2];
                ldmx4(a, &As[(wm * 16 + arow) * 520 + k0 + acol]);
                #pragma unroll
                for (int nt = 0; nt < 2; nt++) {
                    const __half* bp = &Us[(wn * 16 + nt * 8 + (lane >> 2)) * 520 + k0 + ((lane & 3) << 1)];
                    b[nt][0] = *(const unsigned*)bp;
                    b[nt][1] = *(const unsigned*)(bp + 8);
                }
                #pragma unroll
                for (int nt = 0; nt < 2; nt++)
                    mma16816(acc[nt], a, b[nt]);
            }
        }

        // gate exchange: frags -> pre[gate][b][j]
        #pragma unroll
        for (int nt = 0; nt < 2; nt++) {
            int gate = wn * 2 + nt;
            int jloc = (lane & 3) << 1;
            int b = wm * 16 + (lane >> 2);
            *(float2*)&pre[(gate * 64 + b) * 10 + jloc]     = make_float2(acc[nt][0], acc[nt][1]);
            *(float2*)&pre[(gate * 64 + b + 8) * 10 + jloc] = make_float2(acc[nt][2], acc[nt][3]);
        }
        __syncthreads();

        // pointwise LSTM cell (gate order f,g,i,o); 2 cols per thread
        __half* hnext = &g_h16[dir][(t + 1) & 1][0][0];
        float2 pf = *(float2*)&pre[(0 * 64 + pb) * 10 + pj];
        float2 pg = *(float2*)&pre[(1 * 64 + pb) * 10 + pj];
        float2 pi = *(float2*)&pre[(2 * 64 + pb) * 10 + pj];
        float2 po = *(float2*)&pre[(3 * 64 + pb) * 10 + pj];
        float hn[2];
        #pragma unroll
        for (int q = 0; q < 2; q++) {
            float f = sig_fast((q ? pf.y : pf.x) + (q ? xr[0].y : xr[0].x));
            float g = tanh_fast((q ? pg.y : pg.x) + (q ? xr[1].y : xr[1].x));
            float i = sig_fast((q ? pi.y : pi.x) + (q ? xr[2].y : xr[2].x));
            float o = sig_fast((q ? po.y : po.x) + (q ? xr[3].y : xr[3].x));
            creg[q] = creg[q] * f + g * i;
            hn[q] = o * tanh_fast(creg[q]);
        }
        *(__half2*)&hnext[pb * HH + h0 + pj] = __floats2half2_rn(hn[0], hn[1]);

        __syncthreads();                 // all h stores done CTA-wide
        flag_publish(dir, slice, (unsigned)(t + 2));

        // overlapped with barrier wait: out store + next xw prefetch
        *(float2*)&out[(size_t)((s << 6) + pb) * 1024 + dir * HH + h0 + pj] = make_float2(hn[0], hn[1]);
        if (t + 1 < SS) {
            const int sn = dir ? (SS - 2 - t) : (t + 1);
            #pragma unroll
            for (int g2 = 0; g2 < 4; g2++)
                xr[g2] = __half22float2(*(const __half2*)&g_xw16[dir * 4 + g2][(size_t)pb * 512 + sn][h0 + pj]);
        }

        flag_wait_all(dir, (unsigned)(t + 2));
    }
}

// ---------------- phase 3: finalize h_f / h_b from mask ----------------
__global__ void final_kernel(const unsigned char* __restrict__ mask,
                             float* __restrict__ out)
{
    const int b = blockIdx.x;
    const int tid = threadIdx.x;

    __shared__ int mode;  // 1 if mask stored as int32, 0 if uint8
    if (tid == 0)
        mode = (mask[0] == 1 && mask[1] == 0 && mask[2] == 0 && mask[3] == 0) ? 1 : 0;
    __syncthreads();

    int v;
    if (mode) {
        const int* mi = (const int*)mask;
        v = (mi[b * SS + tid] != 0) ? 1 : 0;
    } else {
        v = (mask[b * SS + tid] != 0) ? 1 : 0;
    }
    int len = __syncthreads_count(v);
    int idx = (len > 0) ? (len - 1) : 0;

    float* hf = out + (size_t)SS * BB * 1024;
    float* hb = hf + (size_t)BB * HH;
    hf[b * HH + tid] = out[(size_t)((idx << 6) + b) * 1024 + tid];
    hb[b * HH + tid] = out[(size_t)b * 1024 + HH + tid];
}

// ---------------- launch ----------------
extern "C" void kernel_launch(void* const* d_in, const int* in_sizes, int n_in,
                              void* d_out, int out_size)
{
    const float* x  = (const float*)d_in[0];
    const unsigned char* mask = (const unsigned char*)d_in[1];
    const float* Uf = (const float*)d_in[2];
    const float* Wf = (const float*)d_in[3];
    const float* bf = (const float*)d_in[4];
    const float* Ub = (const float*)d_in[5];
    const float* Wb = (const float*)d_in[6];
    const float* bb = (const float*)d_in[7];
    float* out = (float*)d_out;

    init_kernel<<<1, 256>>>();

    cvt_x_kernel<<<BB * SS * II / 4 / 256, 256>>>(x);
    dim3 wg(16, 16, 8);
    cvt_w_kernel<<<wg, 256>>>(Wf, Wb);

    size_t psmem = (size_t)(2 * 128 * 72 + 2 * 64 * 72) * sizeof(__half);  // 55,296 B
    cudaFuncSetAttribute(proj_kernel, cudaFuncAttributeMaxDynamicSharedMemorySize, (int)psmem);
    dim3 pg(BB * SS / 128, HH / 64, 8);   // (256, 8, 8)
    proj_kernel<<<pg, 256, psmem>>>(bf, bb);

    size_t smem = (size_t)(64 * 520 + 32 * 520) * sizeof(__half)
                + (size_t)(4 * 64 * 10) * sizeof(float);   // 110,080 B
    cudaFuncSetAttribute(lstm_kernel, cudaFuncAttributeMaxDynamicSharedMemorySize, (int)smem);
    lstm_kernel<<<128, 256, smem>>>(Uf, Ub, out);

    final_kernel<<<BB, SS>>>(mask, out);
}

// round 9
// speedup vs baseline: 1.8588x; 1.1885x over previous
#include <cuda_runtime.h>
#include <cuda_fp16.h>
#include <math.h>

#define SS 512   // seq len
#define BB 64    // batch
#define HH 512   // hidden
#define II 512   // input
#define NG 16    // CTAs per barrier group (one b-block)

// ---------------- device scratch (no allocs allowed) ----------------
__device__ __half g_x16[BB * SS][II];        // fp16 copy of x, 33.5 MB
__device__ __half g_w16[8][HH][II];          // W transposed [z][n][k], 4.2 MB
__device__ __half g_xw16[8][BB * SS][HH];    // xw fp16, 268 MB
__device__ __half g_h16[2][2][BB][HH];       // h double buffer per direction
__device__ unsigned int g_flag[2][64][8];    // per-CTA progress flags, 32B padded

// ---------------- PTX helpers ----------------
__device__ __forceinline__ void mma16816(float* c, const unsigned* a, const unsigned* b) {
    asm volatile(
        "mma.sync.aligned.m16n8k16.row.col.f32.f16.f16.f32 "
        "{%0,%1,%2,%3}, {%4,%5,%6,%7}, {%8,%9}, {%0,%1,%2,%3};\n"
        : "+f"(c[0]), "+f"(c[1]), "+f"(c[2]), "+f"(c[3])
        : "r"(a[0]), "r"(a[1]), "r"(a[2]), "r"(a[3]), "r"(b[0]), "r"(b[1]));
}

__device__ __forceinline__ void ldmx4(unsigned* a, const void* p) {
    unsigned addr = (unsigned)__cvta_generic_to_shared(p);
    asm volatile("ldmatrix.sync.aligned.m8n8.x4.shared.b16 {%0,%1,%2,%3}, [%4];"
                 : "=r"(a[0]), "=r"(a[1]), "=r"(a[2]), "=r"(a[3]) : "r"(addr));
}

__device__ __forceinline__ void cpa16(void* s, const void* g) {
    unsigned sa = (unsigned)__cvta_generic_to_shared(s);
    asm volatile("cp.async.cg.shared.global [%0], [%1], 16;" :: "r"(sa), "l"(g));
}
#define CP_COMMIT() asm volatile("cp.async.commit_group;")
#define CP_WAIT(n)  asm volatile("cp.async.wait_group %0;" :: "n"(n))

__device__ __forceinline__ float tanhap(float x) {
    float y;
    asm("tanh.approx.f32 %0, %1;" : "=f"(y) : "f"(x));
    return y;
}
__device__ __forceinline__ float sig_fast(float x) {
    return fmaf(0.5f, tanhap(0.5f * x), 0.5f);
}

// ---------------- flag barrier: per-CTA slot, no atomics ----------------
__device__ __forceinline__ void flag_publish(int dir, int slice, unsigned gen) {
    if (threadIdx.x == 0)
        asm volatile("st.release.gpu.global.u32 [%0], %1;"
                     :: "l"(&g_flag[dir][slice][0]), "r"(gen) : "memory");
}
// wait on the NG flags of this CTA's group (slices gbase..gbase+NG-1)
__device__ __forceinline__ void flag_wait_group(int dir, int gbase, unsigned gen) {
    if (threadIdx.x < NG) {
        const unsigned* p = &g_flag[dir][gbase + threadIdx.x][0];
        unsigned v;
        do {
            asm volatile("ld.acquire.gpu.global.u32 %0, [%1];"
                         : "=r"(v) : "l"(p) : "memory");
        } while (v < gen);
    }
    __syncthreads();
}

// ---------------- init: reset flags every launch ----------------
__global__ void init_kernel() {
    unsigned* p = &g_flag[0][0][0];
    for (int i = threadIdx.x; i < 2 * 64 * 8; i += blockDim.x) p[i] = 0;
}

// ---------------- converts: x -> fp16, W -> fp16 transposed ----------------
__global__ __launch_bounds__(256) void cvt_x_kernel(const float* __restrict__ x) {
    int i4 = blockIdx.x * 256 + threadIdx.x;
    float4 v = *(const float4*)&x[(size_t)i4 * 4];
    __half2* dst = (__half2*)&g_x16[0][0];
    dst[i4 * 2]     = __floats2half2_rn(v.x, v.y);
    dst[i4 * 2 + 1] = __floats2half2_rn(v.z, v.w);
}

__global__ __launch_bounds__(256) void cvt_w_kernel(
    const float* __restrict__ Wf, const float* __restrict__ Wb) {
    const int z = blockIdx.z;
    const float* W = (z < 4 ? Wf : Wb) + (size_t)(z & 3) * II * HH;
    __shared__ float t[32][33];
    const int tx = threadIdx.x & 31, ty = threadIdx.x >> 5;  // 32 x 8
    const int k0 = blockIdx.y * 32, n0 = blockIdx.x * 32;
    #pragma unroll
    for (int i = 0; i < 4; i++)
        t[ty + 8 * i][tx] = W[(size_t)(k0 + ty + 8 * i) * HH + n0 + tx];
    __syncthreads();
    #pragma unroll
    for (int i = 0; i < 4; i++)
        g_w16[z][n0 + ty + 8 * i][k0 + tx] = __float2half_rn(t[tx][ty + 8 * i]);
}

// ---------------- phase 1: input projection GEMM (fp16, 128x128 tiles) ----------------
// CTA 128(M) x 128(N), K-chunk 32, 2-stage cp.async. 8 warps = 4m x 2n, warp tile 32x64.
__global__ __launch_bounds__(256, 2) void proj_kernel(
    const float* __restrict__ bf, const float* __restrict__ bb)
{
    const int z = blockIdx.z;
    const float* bias = (z < 4 ? bf : bb) + (z & 3) * HH;
    const int m0 = blockIdx.x * 128;
    const int n0 = blockIdx.y * 128;

    extern __shared__ __align__(16) __half psm[];
    __half* As = psm;                 // [2][128][40]
    __half* Bs = psm + 2 * 128 * 40;  // [2][128][40]

    const int tid  = threadIdx.x;
    const int lane = tid & 31;
    const int wid  = tid >> 5;
    const int wm   = wid & 3;    // 32-row m tile
    const int wn   = wid >> 2;   // 64-col n tile
    const int arow = (lane & 7) | (((lane >> 3) & 1) << 3);
    const int acol = (lane >> 4) << 3;

    float acc[2][8][4];
    #pragma unroll
    for (int i = 0; i < 2; i++)
        #pragma unroll
        for (int jj = 0; jj < 8; jj++)
            #pragma unroll
            for (int q = 0; q < 4; q++) acc[i][jj][q] = 0.f;

    auto issue = [&](int st, int kc) {
        __half* a = As + st * 128 * 40;
        __half* b = Bs + st * 128 * 40;
        #pragma unroll
        for (int w = 0; w < 2; w++) {          // A: 128 rows x 4 units (32 cols)
            int f = tid + w * 256;
            int row = f >> 2, u = f & 3;
            cpa16(&a[row * 40 + u * 8], &g_x16[m0 + row][kc + u * 8]);
        }
        #pragma unroll
        for (int w = 0; w < 2; w++) {          // B: 128 rows x 4 units
            int f = tid + w * 256;
            int row = f >> 2, u = f & 3;
            cpa16(&b[row * 40 + u * 8], &g_w16[z][n0 + row][kc + u * 8]);
        }
        CP_COMMIT();
    };

    issue(0, 0);
    for (int kb = 0; kb < 16; kb++) {
        const int cur = kb & 1;
        if (kb < 15) { issue(cur ^ 1, (kb + 1) * 32); CP_WAIT(1); }
        else         { CP_WAIT(0); }
        __syncthreads();
        const __half* a0 = As + cur * 128 * 40;
        const __half* b0 = Bs + cur * 128 * 40;
        #pragma unroll
        for (int k16 = 0; k16 < 2; k16++) {
            const int k0 = k16 * 16;
            unsigned a[2][4], b[8][2];
            #pragma unroll
            for (int mt = 0; mt < 2; mt++)
                ldmx4(a[mt], &a0[(wm * 32 + mt * 16 + arow) * 40 + k0 + acol]);
            #pragma unroll
            for (int nt = 0; nt < 8; nt++) {
                const __half* bp = &b0[(wn * 64 + nt * 8 + (lane >> 2)) * 40 + k0 + ((lane & 3) << 1)];
                b[nt][0] = *(const unsigned*)bp;
                b[nt][1] = *(const unsigned*)(bp + 8);
            }
            #pragma unroll
            for (int mt = 0; mt < 2; mt++)
                #pragma unroll
                for (int nt = 0; nt < 8; nt++)
                    mma16816(acc[mt][nt], a[mt], b[nt]);
        }
        __syncthreads();
    }

    #pragma unroll
    for (int mt = 0; mt < 2; mt++) {
        #pragma unroll
        for (int nt = 0; nt < 8; nt++) {
            int n = n0 + wn * 64 + nt * 8 + ((lane & 3) << 1);
            float bx = bias[n], by = bias[n + 1];
            int mA = m0 + wm * 32 + mt * 16 + (lane >> 2);
            *(__half2*)&g_xw16[z][mA][n]     = __floats2half2_rn(acc[mt][nt][0] + bx, acc[mt][nt][1] + by);
            *(__half2*)&g_xw16[z][mA + 8][n] = __floats2half2_rn(acc[mt][nt][2] + bx, acc[mt][nt][3] + by);
        }
    }
}

// ---------------- phase 2: persistent recurrent kernel ----------------
// 128 CTAs: dir = bid>>6, slice = bid&63; bblk = slice>>4 (16 batches), hblk = slice&15 (32 h-cols).
// 8 independent 16-CTA groups (dir x bblk). Per step per CTA:
//   preact[16b x 128(4g x 32h)] = h16[b-block 16 x 512] @ Uslice[512 x 128]
// 8 warps, each one 16x16 n-tile over full K. Gates thread-local after smem exchange.
__global__ void __launch_bounds__(256, 1) lstm_kernel(
    const float* __restrict__ Uf, const float* __restrict__ Ub,
    float* __restrict__ out)
{
    const int dir   = blockIdx.x >> 6;
    const int slice = blockIdx.x & 63;
    const int bblk  = slice >> 4;
    const int hblk  = slice & 15;
    const int b0    = bblk * 16;
    const int h0g   = hblk * 32;
    const int gbase = bblk * 16;

    extern __shared__ __align__(16) char smraw[];
    __half* As  = (__half*)smraw;            // [16][520]   h tile (16 rows x 512)
    __half* Us  = As + 16 * 520;             // [128][520]  U slice, col c = g*32+jj
    float*  pre = (float*)(Us + 128 * 520);  // [4][16][34] gate exchange

    const int tid  = threadIdx.x;
    const int lane = tid & 31;
    const int wid  = tid >> 5;               // n-tile: cols wid*16 .. +15
    const int arow = (lane & 7) | (((lane >> 3) & 1) << 3);
    const int acol = (lane >> 4) << 3;

    // pointwise mapping: 2 values/thread (16b x 32j = 512 vals)
    const int pb = tid >> 4;            // 0..15 (local batch)
    const int pj = (tid & 15) << 1;     // 0..30 (local h col pair)

    const float* U = dir ? Ub : Uf;     // [4][HH][HH]

    // U slice -> fp16 smem: Us[c][k] = U[g][k][h0g + jj], c = g*32 + jj
    for (int idx = tid; idx < 128 * 512; idx += 256) {
        int c = idx & 127, k = idx >> 7;
        Us[c * 520 + k] = __float2half_rn(U[((size_t)(c >> 5) * HH + k) * HH + h0g + (c & 31)]);
    }
    // zero own h slice in buffer 0
    *(__half2*)&g_h16[dir][0][b0 + pb][h0g + pj] = __floats2half2_rn(0.f, 0.f);

    float creg[2] = {0.f, 0.f};

    __syncthreads();
    flag_publish(dir, slice, 1u);

    // prefetch xw for t=0
    float2 xr[4];
    {
        const int s0 = dir ? (SS - 1) : 0;
        #pragma unroll
        for (int g2 = 0; g2 < 4; g2++)
            xr[g2] = __half22float2(*(const __half2*)&g_xw16[dir * 4 + g2][(size_t)(b0 + pb) * 512 + s0][h0g + pj]);
    }

    flag_wait_group(dir, gbase, 1u);

    for (int t = 0; t < SS; t++) {
        const int s = dir ? (SS - 1 - t) : t;
        const __half* hprev = &g_h16[dir][t & 1][0][0];

        // bulk load h[b-block][512] : 16 KB, one group
        #pragma unroll
        for (int w = 0; w < 4; w++) {
            int f = tid + w * 256;           // 1024 units
            int row = f >> 6, u = f & 63;
            cpa16(&As[row * 520 + u * 8], &hprev[(size_t)(b0 + row) * 512 + u * 8]);
        }
        CP_COMMIT();
        CP_WAIT(0);
        __syncthreads();

        float acc[2][4];
        #pragma unroll
        for (int a2 = 0; a2 < 2; a2++)
            #pragma unroll
            for (int q = 0; q < 4; q++) acc[a2][q] = 0.f;

        #pragma unroll
        for (int k16 = 0; k16 < 32; k16++) {
            const int k0 = k16 * 16;
            unsigned a[4], b[2][2];
            ldmx4(a, &As[arow * 520 + k0 + acol]);
            #pragma unroll
            for (int nt = 0; nt < 2; nt++) {
                const __half* bp = &Us[(wid * 16 + nt * 8 + (lane >> 2)) * 520 + k0 + ((lane & 3) << 1)];
                b[nt][0] = *(const unsigned*)bp;
                b[nt][1] = *(const unsigned*)(bp + 8);
            }
            #pragma unroll
            for (int nt = 0; nt < 2; nt++)
                mma16816(acc[nt], a, b[nt]);
        }

        // gate exchange: frag cols c = wid*16 + nt*8 + (lane&3)*2 -> pre[g][row][jj]
        #pragma unroll
        for (int nt = 0; nt < 2; nt++) {
            int c = wid * 16 + nt * 8 + ((lane & 3) << 1);
            int g = c >> 5, jj = c & 31;
            int r = lane >> 2;
            *(float2*)&pre[(g * 16 + r) * 34 + jj]     = make_float2(acc[nt][0], acc[nt][1]);
            *(float2*)&pre[(g * 16 + r + 8) * 34 + jj] = make_float2(acc[nt][2], acc[nt][3]);
        }
        __syncthreads();

        // pointwise LSTM cell (gate order f,g,i,o)
        __half* hnext = &g_h16[dir][(t + 1) & 1][0][0];
        float2 pf = *(float2*)&pre[(0 * 16 + pb) * 34 + pj];
        float2 pg = *(float2*)&pre[(1 * 16 + pb) * 34 + pj];
        float2 pi = *(float2*)&pre[(2 * 16 + pb) * 34 + pj];
        float2 po = *(float2*)&pre[(3 * 16 + pb) * 34 + pj];
        float hn[2];
        #pragma unroll
        for (int q = 0; q < 2; q++) {
            float f = sig_fast((q ? pf.y : pf.x) + (q ? xr[0].y : xr[0].x));
            float g = tanhap((q ? pg.y : pg.x) + (q ? xr[1].y : xr[1].x));
            float i = sig_fast((q ? pi.y : pi.x) + (q ? xr[2].y : xr[2].x));
            float o = sig_fast((q ? po.y : po.x) + (q ? xr[3].y : xr[3].x));
            creg[q] = creg[q] * f + g * i;
            hn[q] = o * tanhap(creg[q]);
        }
        *(__half2*)&hnext[(size_t)(b0 + pb) * 512 + h0g + pj] = __floats2half2_rn(hn[0], hn[1]);

        __syncthreads();                 // all h stores done CTA-wide
        flag_publish(dir, slice, (unsigned)(t + 2));

        // overlapped with barrier wait: out store + next xw prefetch
        *(float2*)&out[(size_t)((s << 6) + b0 + pb) * 1024 + dir * HH + h0g + pj] = make_float2(hn[0], hn[1]);
        if (t + 1 < SS) {
            const int sn = dir ? (SS - 2 - t) : (t + 1);
            #pragma unroll
            for (int g2 = 0; g2 < 4; g2++)
                xr[g2] = __half22float2(*(const __half2*)&g_xw16[dir * 4 + g2][(size_t)(b0 + pb) * 512 + sn][h0g + pj]);
        }

        flag_wait_group(dir, gbase, (unsigned)(t + 2));
    }
}

// ---------------- phase 3: finalize h_f / h_b from mask ----------------
__global__ void final_kernel(const unsigned char* __restrict__ mask,
                             float* __restrict__ out)
{
    const int b = blockIdx.x;
    const int tid = threadIdx.x;

    __shared__ int mode;  // 1 if mask stored as int32, 0 if uint8
    if (tid == 0)
        mode = (mask[0] == 1 && mask[1] == 0 && mask[2] == 0 && mask[3] == 0) ? 1 : 0;
    __syncthreads();

    int v;
    if (mode) {
        const int* mi = (const int*)mask;
        v = (mi[b * SS + tid] != 0) ? 1 : 0;
    } else {
        v = (mask[b * SS + tid] != 0) ? 1 : 0;
    }
    int len = __syncthreads_count(v);
    int idx = (len > 0) ? (len - 1) : 0;

    float* hf = out + (size_t)SS * BB * 1024;
    float* hb = hf + (size_t)BB * HH;
    hf[b * HH + tid] = out[(size_t)((idx << 6) + b) * 1024 + tid];
    hb[b * HH + tid] = out[(size_t)b * 1024 + HH + tid];
}

// ---------------- launch ----------------
extern "C" void kernel_launch(void* const* d_in, const int* in_sizes, int n_in,
                              void* d_out, int out_size)
{
    const float* x  = (const float*)d_in[0];
    const unsigned char* mask = (const unsigned char*)d_in[1];
    const float* Uf = (const float*)d_in[2];
    const float* Wf = (const float*)d_in[3];
    const float* bf = (const float*)d_in[4];
    const float* Ub = (const float*)d_in[5];
    const float* Wb = (const float*)d_in[6];
    const float* bb = (const float*)d_in[7];
    float* out = (float*)d_out;

    init_kernel<<<1, 256>>>();

    cvt_x_kernel<<<BB * SS * II / 4 / 256, 256>>>(x);
    dim3 wg(16, 16, 8);
    cvt_w_kernel<<<wg, 256>>>(Wf, Wb);

    size_t psmem = (size_t)(4 * 128 * 40) * sizeof(__half);   // 40,960 B
    cudaFuncSetAttribute(proj_kernel, cudaFuncAttributeMaxDynamicSharedMemorySize, (int)psmem);
    dim3 pg(BB * SS / 128, HH / 128, 8);   // (256, 4, 8)
    proj_kernel<<<pg, 256, psmem>>>(bf, bb);

    size_t smem = (size_t)(16 * 520 + 128 * 520) * sizeof(__half)
                + (size_t)(4 * 16 * 34) * sizeof(float);      // 158,464 B
    cudaFuncSetAttribute(lstm_kernel, cudaFuncAttributeMaxDynamicSharedMemorySize, (int)smem);
    lstm_kernel<<<128, 256, smem>>>(Uf, Ub, out);

    final_kernel<<<BB, SS>>>(mask, out);
}

// round 10
// speedup vs baseline: 1.8790x; 1.0109x over previous
#include <cuda_runtime.h>
#include <cuda_fp16.h>
#include <math.h>

#define SS 512   // seq len
#define BB 64    // batch
#define HH 512   // hidden
#define II 512   // input
#define NG 16    // CTAs per barrier group (one b-block)

// ---------------- device scratch (no allocs allowed) ----------------
__device__ __half g_x16[BB * SS][II];        // fp16 copy of x, 33.5 MB
__device__ __half g_w16[8][HH][II];          // W transposed [z][n][k], 4.2 MB
__device__ __half g_xw16[8][BB * SS][HH];    // xw fp16, 268 MB
__device__ __half g_h16[2][2][BB][HH];       // h double buffer per direction
__device__ unsigned int g_flag[2][64][8];    // per-CTA progress flags, 32B padded

// ---------------- PTX helpers ----------------
__device__ __forceinline__ void mma16816(float* c, const unsigned* a, const unsigned* b) {
    asm volatile(
        "mma.sync.aligned.m16n8k16.row.col.f32.f16.f16.f32 "
        "{%0,%1,%2,%3}, {%4,%5,%6,%7}, {%8,%9}, {%0,%1,%2,%3};\n"
        : "+f"(c[0]), "+f"(c[1]), "+f"(c[2]), "+f"(c[3])
        : "r"(a[0]), "r"(a[1]), "r"(a[2]), "r"(a[3]), "r"(b[0]), "r"(b[1]));
}

__device__ __forceinline__ void ldmx4(unsigned* a, const void* p) {
    unsigned addr = (unsigned)__cvta_generic_to_shared(p);
    asm volatile("ldmatrix.sync.aligned.m8n8.x4.shared.b16 {%0,%1,%2,%3}, [%4];"
                 : "=r"(a[0]), "=r"(a[1]), "=r"(a[2]), "=r"(a[3]) : "r"(addr));
}

__device__ __forceinline__ void cpa16(void* s, const void* g) {
    unsigned sa = (unsigned)__cvta_generic_to_shared(s);
    asm volatile("cp.async.cg.shared.global [%0], [%1], 16;" :: "r"(sa), "l"(g));
}
#define CP_COMMIT() asm volatile("cp.async.commit_group;")
#define CP_WAIT(n)  asm volatile("cp.async.wait_group %0;" :: "n"(n))

__device__ __forceinline__ float tanhap(float x) {
    float y;
    asm("tanh.approx.f32 %0, %1;" : "=f"(y) : "f"(x));
    return y;
}
__device__ __forceinline__ float sig_fast(float x) {
    return fmaf(0.5f, tanhap(0.5f * x), 0.5f);
}

// ---------------- flag barrier: per-CTA slot, no atomics ----------------
__device__ __forceinline__ void flag_publish(int dir, int slice, unsigned gen) {
    if (threadIdx.x == 0)
        asm volatile("st.release.gpu.global.u32 [%0], %1;"
                     :: "l"(&g_flag[dir][slice][0]), "r"(gen) : "memory");
}
__device__ __forceinline__ void flag_wait_group(int dir, int gbase, unsigned gen) {
    if (threadIdx.x < NG) {
        const unsigned* p = &g_flag[dir][gbase + threadIdx.x][0];
        unsigned v;
        do {
            asm volatile("ld.acquire.gpu.global.u32 %0, [%1];"
                         : "=r"(v) : "l"(p) : "memory");
        } while (v < gen);
    }
    __syncthreads();
}

// ---------------- init: reset flags every launch ----------------
__global__ void init_kernel() {
    unsigned* p = &g_flag[0][0][0];
    for (int i = threadIdx.x; i < 2 * 64 * 8; i += blockDim.x) p[i] = 0;
}

// ---------------- converts: x -> fp16, W -> fp16 transposed ----------------
__global__ __launch_bounds__(256) void cvt_x_kernel(const float* __restrict__ x) {
    int i4 = blockIdx.x * 256 + threadIdx.x;
    float4 v = *(const float4*)&x[(size_t)i4 * 4];
    __half2* dst = (__half2*)&g_x16[0][0];
    dst[i4 * 2]     = __floats2half2_rn(v.x, v.y);
    dst[i4 * 2 + 1] = __floats2half2_rn(v.z, v.w);
}

__global__ __launch_bounds__(256) void cvt_w_kernel(
    const float* __restrict__ Wf, const float* __restrict__ Wb) {
    const int z = blockIdx.z;
    const float* W = (z < 4 ? Wf : Wb) + (size_t)(z & 3) * II * HH;
    __shared__ float t[32][33];
    const int tx = threadIdx.x & 31, ty = threadIdx.x >> 5;  // 32 x 8
    const int k0 = blockIdx.y * 32, n0 = blockIdx.x * 32;
    #pragma unroll
    for (int i = 0; i < 4; i++)
        t[ty + 8 * i][tx] = W[(size_t)(k0 + ty + 8 * i) * HH + n0 + tx];
    __syncthreads();
    #pragma unroll
    for (int i = 0; i < 4; i++)
        g_w16[z][n0 + ty + 8 * i][k0 + tx] = __float2half_rn(t[tx][ty + 8 * i]);
}

// ---------------- phase 1: input projection GEMM (fp16, 128x128 tiles) ----------------
// CTA 128(M) x 128(N), K-chunk 32, 2-stage cp.async. 8 warps = 4m x 2n, warp tile 32x64.
// B operand via ldmatrix.x4 (2 per k16 for 64 n-cols).
__global__ __launch_bounds__(256, 2) void proj_kernel(
    const float* __restrict__ bf, const float* __restrict__ bb)
{
    const int z = blockIdx.z;
    const float* bias = (z < 4 ? bf : bb) + (z & 3) * HH;
    const int m0 = blockIdx.x * 128;
    const int n0 = blockIdx.y * 128;

    extern __shared__ __align__(16) __half psm[];
    __half* As = psm;                 // [2][128][40]
    __half* Bs = psm + 2 * 128 * 40;  // [2][128][40]

    const int tid  = threadIdx.x;
    const int lane = tid & 31;
    const int wid  = tid >> 5;
    const int wm   = wid & 3;    // 32-row m tile
    const int wn   = wid >> 2;   // 64-col n tile
    const int lrow = (lane & 15);
    const int lcol = (lane >> 4) << 3;

    float acc[2][8][4];
    #pragma unroll
    for (int i = 0; i < 2; i++)
        #pragma unroll
        for (int jj = 0; jj < 8; jj++)
            #pragma unroll
            for (int q = 0; q < 4; q++) acc[i][jj][q] = 0.f;

    auto issue = [&](int st, int kc) {
        __half* a = As + st * 128 * 40;
        __half* b = Bs + st * 128 * 40;
        #pragma unroll
        for (int w = 0; w < 2; w++) {
            int f = tid + w * 256;
            int row = f >> 2, u = f & 3;
            cpa16(&a[row * 40 + u * 8], &g_x16[m0 + row][kc + u * 8]);
        }
        #pragma unroll
        for (int w = 0; w < 2; w++) {
            int f = tid + w * 256;
            int row = f >> 2, u = f & 3;
            cpa16(&b[row * 40 + u * 8], &g_w16[z][n0 + row][kc + u * 8]);
        }
        CP_COMMIT();
    };

    issue(0, 0);
    for (int kb = 0; kb < 16; kb++) {
        const int cur = kb & 1;
        if (kb < 15) { issue(cur ^ 1, (kb + 1) * 32); CP_WAIT(1); }
        else         { CP_WAIT(0); }
        __syncthreads();
        const __half* a0 = As + cur * 128 * 40;
        const __half* b0 = Bs + cur * 128 * 40;
        #pragma unroll
        for (int k16 = 0; k16 < 2; k16++) {
            const int k0 = k16 * 16;
            unsigned a[2][4], bbm[2][4];
            #pragma unroll
            for (int mt = 0; mt < 2; mt++)
                ldmx4(a[mt], &a0[(wm * 32 + mt * 16 + lrow) * 40 + k0 + lcol]);
            #pragma unroll
            for (int ntp = 0; ntp < 2; ntp++)
                ldmx4(bbm[ntp], &b0[(wn * 64 + ntp * 16 + lrow) * 40 + k0 + lcol]);
            #pragma unroll
            for (int mt = 0; mt < 2; mt++)
                #pragma unroll
                for (int nt = 0; nt < 4; nt++) {
                    // nt 0..3 covers 32 cols of this k-slab via 2 ldmx4s; second 32 handled below
                    unsigned b[2] = { bbm[nt >> 1][nt & 1], bbm[nt >> 1][(nt & 1) + 2] };
                    mma16816(acc[mt][nt], a[mt], b);
                }
        }
        // second half of n (cols 32..63 of warp tile)
        #pragma unroll
        for (int k16 = 0; k16 < 2; k16++) {
            const int k0 = k16 * 16;
            unsigned a[2][4], bbm[2][4];
            #pragma unroll
            for (int mt = 0; mt < 2; mt++)
                ldmx4(a[mt], &a0[(wm * 32 + mt * 16 + lrow) * 40 + k0 + lcol]);
            #pragma unroll
            for (int ntp = 0; ntp < 2; ntp++)
                ldmx4(bbm[ntp], &b0[(wn * 64 + 32 + ntp * 16 + lrow) * 40 + k0 + lcol]);
            #pragma unroll
            for (int mt = 0; mt < 2; mt++)
                #pragma unroll
                for (int nt = 0; nt < 4; nt++) {
                    unsigned b[2] = { bbm[nt >> 1][nt & 1], bbm[nt >> 1][(nt & 1) + 2] };
                    mma16816(acc[mt][nt + 4], a[mt], b);
                }
        }
        __syncthreads();
    }

    #pragma unroll
    for (int mt = 0; mt < 2; mt++) {
        #pragma unroll
        for (int nt = 0; nt < 8; nt++) {
            int n = n0 + wn * 64 + nt * 8 + ((lane & 3) << 1);
            float bx = bias[n], by = bias[n + 1];
            int mA = m0 + wm * 32 + mt * 16 + (lane >> 2);
            *(__half2*)&g_xw16[z][mA][n]     = __floats2half2_rn(acc[mt][nt][0] + bx, acc[mt][nt][1] + by);
            *(__half2*)&g_xw16[z][mA + 8][n] = __floats2half2_rn(acc[mt][nt][2] + bx, acc[mt][nt][3] + by);
        }
    }
}

// ---------------- phase 2: persistent recurrent kernel ----------------
// 128 CTAs: dir = bid>>6, slice = bid&63; bblk = slice>>4 (16 batches), hblk = slice&15 (32 h-cols).
// 8 independent 16-CTA groups. preact[16b x 128] = h[16x512] @ Uslice[512x128].
// 8 warps, 16x16 n-tiles; B-frags via one ldmatrix.x4 per k16.
__global__ void __launch_bounds__(256, 1) lstm_kernel(
    const float* __restrict__ Uf, const float* __restrict__ Ub,
    float* __restrict__ out)
{
    const int dir   = blockIdx.x >> 6;
    const int slice = blockIdx.x & 63;
    const int bblk  = slice >> 4;
    const int hblk  = slice & 15;
    const int b0    = bblk * 16;
    const int h0g   = hblk * 32;
    const int gbase = bblk * 16;

    extern __shared__ __align__(16) char smraw[];
    __half* As  = (__half*)smraw;            // [16][520]
    __half* Us  = As + 16 * 520;             // [128][520]  col c = g*32+jj
    float*  pre = (float*)(Us + 128 * 520);  // [4][16][34]

    const int tid  = threadIdx.x;
    const int lane = tid & 31;
    const int wid  = tid >> 5;
    const int lrow = (lane & 15);
    const int lcol = (lane >> 4) << 3;

    const int pb = tid >> 4;            // 0..15 (local batch)
    const int pj = (tid & 15) << 1;     // 0..30 (local h col pair)

    const float* U = dir ? Ub : Uf;     // [4][HH][HH]

    // U slice -> fp16 smem: Us[c][k] = U[g][k][h0g + jj], c = g*32 + jj
    for (int idx = tid; idx < 128 * 512; idx += 256) {
        int c = idx & 127, k = idx >> 7;
        Us[c * 520 + k] = __float2half_rn(U[((size_t)(c >> 5) * HH + k) * HH + h0g + (c & 31)]);
    }
    // zero own h slice in buffer 0
    *(__half2*)&g_h16[dir][0][b0 + pb][h0g + pj] = __floats2half2_rn(0.f, 0.f);

    float creg[2] = {0.f, 0.f};

    __syncthreads();
    flag_publish(dir, slice, 1u);

    float2 xr[4];
    {
        const int s0 = dir ? (SS - 1) : 0;
        #pragma unroll
        for (int g2 = 0; g2 < 4; g2++)
            xr[g2] = __half22float2(*(const __half2*)&g_xw16[dir * 4 + g2][(size_t)(b0 + pb) * 512 + s0][h0g + pj]);
    }

    flag_wait_group(dir, gbase, 1u);

    for (int t = 0; t < SS; t++) {
        const int s = dir ? (SS - 1 - t) : t;
        const __half* hprev = &g_h16[dir][t & 1][0][0];

        // bulk load h[b-block][512] : 16 KB
        #pragma unroll
        for (int w = 0; w < 4; w++) {
            int f = tid + w * 256;
            int row = f >> 6, u = f & 63;
            cpa16(&As[row * 520 + u * 8], &hprev[(size_t)(b0 + row) * 512 + u * 8]);
        }
        CP_COMMIT();
        CP_WAIT(0);
        __syncthreads();

        float acc[2][4];
        #pragma unroll
        for (int a2 = 0; a2 < 2; a2++)
            #pragma unroll
            for (int q = 0; q < 4; q++) acc[a2][q] = 0.f;

        #pragma unroll
        for (int k16 = 0; k16 < 32; k16++) {
            const int k0 = k16 * 16;
            unsigned a[4], bbm[4];
            ldmx4(a, &As[lrow * 520 + k0 + lcol]);
            ldmx4(bbm, &Us[(wid * 16 + lrow) * 520 + k0 + lcol]);
            unsigned bA[2] = { bbm[0], bbm[2] };
            unsigned bB[2] = { bbm[1], bbm[3] };
            mma16816(acc[0], a, bA);
            mma16816(acc[1], a, bB);
        }

        // gate exchange: frag cols c = wid*16 + nt*8 + (lane&3)*2 -> pre[g][row][jj]
        #pragma unroll
        for (int nt = 0; nt < 2; nt++) {
            int c = wid * 16 + nt * 8 + ((lane & 3) << 1);
            int g = c >> 5, jj = c & 31;
            int r = lane >> 2;
            *(float2*)&pre[(g * 16 + r) * 34 + jj]     = make_float2(acc[nt][0], acc[nt][1]);
            *(float2*)&pre[(g * 16 + r + 8) * 34 + jj] = make_float2(acc[nt][2], acc[nt][3]);
        }
        __syncthreads();

        // pointwise LSTM cell (gate order f,g,i,o)
        __half* hnext = &g_h16[dir][(t + 1) & 1][0][0];
        float2 pf = *(float2*)&pre[(0 * 16 + pb) * 34 + pj];
        float2 pg = *(float2*)&pre[(1 * 16 + pb) * 34 + pj];
        float2 pi = *(float2*)&pre[(2 * 16 + pb) * 34 + pj];
        float2 po = *(float2*)&pre[(3 * 16 + pb) * 34 + pj];
        float hn[2];
        #pragma unroll
        for (int q = 0; q < 2; q++) {
            float f = sig_fast((q ? pf.y : pf.x) + (q ? xr[0].y : xr[0].x));
            float g = tanhap((q ? pg.y : pg.x) + (q ? xr[1].y : xr[1].x));
            float i = sig_fast((q ? pi.y : pi.x) + (q ? xr[2].y : xr[2].x));
            float o = sig_fast((q ? po.y : po.x) + (q ? xr[3].y : xr[3].x));
            creg[q] = creg[q] * f + g * i;
            hn[q] = o * tanhap(creg[q]);
        }
        *(__half2*)&hnext[(size_t)(b0 + pb) * 512 + h0g + pj] = __floats2half2_rn(hn[0], hn[1]);

        __syncthreads();
        flag_publish(dir, slice, (unsigned)(t + 2));

        // overlapped with barrier wait: out store + next xw prefetch
        *(float2*)&out[(size_t)((s << 6) + b0 + pb) * 1024 + dir * HH + h0g + pj] = make_float2(hn[0], hn[1]);
        if (t + 1 < SS) {
            const int sn = dir ? (SS - 2 - t) : (t + 1);
            #pragma unroll
            for (int g2 = 0; g2 < 4; g2++)
                xr[g2] = __half22float2(*(const __half2*)&g_xw16[dir * 4 + g2][(size_t)(b0 + pb) * 512 + sn][h0g + pj]);
        }

        flag_wait_group(dir, gbase, (unsigned)(t + 2));
    }
}

// ---------------- phase 3: finalize h_f / h_b from mask ----------------
__global__ void final_kernel(const unsigned char* __restrict__ mask,
                             float* __restrict__ out)
{
    const int b = blockIdx.x;
    const int tid = threadIdx.x;

    __shared__ int mode;  // 1 if mask stored as int32, 0 if uint8
    if (tid == 0)
        mode = (mask[0] == 1 && mask[1] == 0 && mask[2] == 0 && mask[3] == 0) ? 1 : 0;
    __syncthreads();

    int v;
    if (mode) {
        const int* mi = (const int*)mask;
        v = (mi[b * SS + tid] != 0) ? 1 : 0;
    } else {
        v = (mask[b * SS + tid] != 0) ? 1 : 0;
    }
    int len = __syncthreads_count(v);
    int idx = (len > 0) ? (len - 1) : 0;

    float* hf = out + (size_t)SS * BB * 1024;
    float* hb = hf + (size_t)BB * HH;
    hf[b * HH + tid] = out[(size_t)((idx << 6) + b) * 1024 + tid];
    hb[b * HH + tid] = out[(size_t)b * 1024 + HH + tid];
}

// ---------------- launch ----------------
extern "C" void kernel_launch(void* const* d_in, const int* in_sizes, int n_in,
                              void* d_out, int out_size)
{
    const float* x  = (const float*)d_in[0];
    const unsigned char* mask = (const unsigned char*)d_in[1];
    const float* Uf = (const float*)d_in[2];
    const float* Wf = (const float*)d_in[3];
    const float* bf = (const float*)d_in[4];
    const float* Ub = (const float*)d_in[5];
    const float* Wb = (const float*)d_in[6];
    const float* bb = (const float*)d_in[7];
    float* out = (float*)d_out;

    init_kernel<<<1, 256>>>();

    cvt_x_kernel<<<BB * SS * II / 4 / 256, 256>>>(x);
    dim3 wg(16, 16, 8);
    cvt_w_kernel<<<wg, 256>>>(Wf, Wb);

    size_t psmem = (size_t)(4 * 128 * 40) * sizeof(__half);   // 40,960 B
    cudaFuncSetAttribute(proj_kernel, cudaFuncAttributeMaxDynamicSharedMemorySize, (int)psmem);
    dim3 pg(BB * SS / 128, HH / 128, 8);   // (256, 4, 8)
    proj_kernel<<<pg, 256, psmem>>>(bf, bb);

    size_t smem = (size_t)(16 * 520 + 128 * 520) * sizeof(__half)
                + (size_t)(4 * 16 * 34) * sizeof(float);      // 158,464 B
    cudaFuncSetAttribute(lstm_kernel, cudaFuncAttributeMaxDynamicSharedMemorySize, (int)smem);
    lstm_kernel<<<128, 256, smem>>>(Uf, Ub, out);

    final_kernel<<<BB, SS>>>(mask, out);
}